// round 5
// baseline (speedup 1.0000x reference)
#include <cuda_runtime.h>
#include <math.h>
#include <stdint.h>

// ---------------- model constants ----------------
#define BB     16
#define EDIM   768
#define NHEADS 12
#define HD     64
#define FFDIM  3072
#define NLAYER 8
#define SEQ    64
#define ROWSM  1024     // BB*SEQ
#define PDIM   4096

// ---------------- scratch (device globals; no allocations allowed) ----------
__device__ float g_pool1[16 * 255 * 255 * 16];
__device__ float g_pool2[16 * 126 * 126 * 16];
__device__ float g_patches[ROWSM * PDIM];
__device__ float g_t [ROWSM * EDIM];
__device__ float g_q [ROWSM * EDIM];
__device__ float g_k [ROWSM * EDIM];
__device__ float g_v [ROWSM * EDIM];
__device__ float g_att[ROWSM * EDIM];
__device__ float g_o1[ROWSM * EDIM];
__device__ float g_f1[ROWSM * FFDIM];
__device__ float g_f2[ROWSM * EDIM];
__device__ float g_part[3 * ROWSM * FFDIM];   // split-K partials (9.4M floats)

// ---------------- conv1 (3x3x3->16) + relu + maxpool2x2, fused -------------
__global__ void conv1_pool_kernel(const float* __restrict__ x,
                                  const float* __restrict__ w,
                                  const float* __restrict__ bias,
                                  float* __restrict__ out) {
    __shared__ float ws[432];
    __shared__ float bs[16];
    int tid = threadIdx.x;
    for (int i = tid; i < 432; i += 256) ws[i] = w[i];
    if (tid < 16) bs[tid] = bias[tid];
    __syncthreads();

    int idx = blockIdx.x * 256 + tid;
    if (idx >= 16 * 255 * 255) return;
    int pw = idx % 255;
    int t  = idx / 255;
    int ph = t % 255;
    int b  = t / 255;

    float mx[16];
#pragma unroll
    for (int c = 0; c < 16; c++) mx[c] = 0.0f;

    for (int dy = 0; dy < 2; dy++) {
        for (int dx = 0; dx < 2; dx++) {
            int h0 = 2 * ph + dy;
            int w0 = 2 * pw + dx;
            float acc[16];
#pragma unroll
            for (int c = 0; c < 16; c++) acc[c] = bs[c];
            for (int kh = 0; kh < 3; kh++) {
                for (int kw = 0; kw < 3; kw++) {
                    const float* xp = x + (((long)(b * 512 + h0 + kh) * 512) + (w0 + kw)) * 3;
                    float x0 = xp[0], x1 = xp[1], x2 = xp[2];
                    const float* wp = ws + ((kh * 3 + kw) * 3) * 16;
#pragma unroll
                    for (int c = 0; c < 16; c++)
                        acc[c] += x0 * wp[c] + x1 * wp[16 + c] + x2 * wp[32 + c];
                }
            }
#pragma unroll
            for (int c = 0; c < 16; c++) mx[c] = fmaxf(mx[c], fmaxf(acc[c], 0.0f));
        }
    }
    float* op = out + (long)idx * 16;
#pragma unroll
    for (int c = 0; c < 16; c++) op[c] = mx[c];
}

// ---------------- conv2 (3x3x16->16) + relu + maxpool2x2, fused ------------
__global__ void conv2_pool_kernel(const float* __restrict__ in,
                                  const float* __restrict__ w,
                                  const float* __restrict__ bias,
                                  float* __restrict__ out) {
    __shared__ float ws[2304];
    __shared__ float bs[16];
    int tid = threadIdx.x;
    for (int i = tid; i < 2304; i += 256) ws[i] = w[i];
    if (tid < 16) bs[tid] = bias[tid];
    __syncthreads();

    int idx = blockIdx.x * 256 + tid;
    if (idx >= 16 * 126 * 126) return;
    int pw = idx % 126;
    int t  = idx / 126;
    int ph = t % 126;
    int b  = t / 126;

    float mx[16];
#pragma unroll
    for (int c = 0; c < 16; c++) mx[c] = 0.0f;

    for (int dy = 0; dy < 2; dy++) {
        for (int dx = 0; dx < 2; dx++) {
            int h0 = 2 * ph + dy;
            int w0 = 2 * pw + dx;
            float acc[16];
#pragma unroll
            for (int c = 0; c < 16; c++) acc[c] = bs[c];
            for (int kh = 0; kh < 3; kh++) {
                for (int kw = 0; kw < 3; kw++) {
                    const float* xp = in + ((long)(b * 255 + h0 + kh) * 255 + (w0 + kw)) * 16;
                    float xv[16];
#pragma unroll
                    for (int ci = 0; ci < 16; ci++) xv[ci] = xp[ci];
                    const float* wp = ws + ((kh * 3 + kw) * 16) * 16;
#pragma unroll
                    for (int ci = 0; ci < 16; ci++) {
#pragma unroll
                        for (int c = 0; c < 16; c++)
                            acc[c] += xv[ci] * wp[ci * 16 + c];
                    }
                }
            }
#pragma unroll
            for (int c = 0; c < 16; c++) mx[c] = fmaxf(mx[c], fmaxf(acc[c], 0.0f));
        }
    }
    float* op = out + (long)idx * 16;
#pragma unroll
    for (int c = 0; c < 16; c++) op[c] = mx[c];
}

// ---------------- patch gather -----------------------------------------------
__global__ void patch_kernel(const float* __restrict__ pool2,
                             float* __restrict__ patches) {
    long idx = (long)blockIdx.x * 256 + threadIdx.x;
    if (idx >= (long)ROWSM * PDIM) return;
    int d   = (int)(idx & (PDIM - 1));
    int row = (int)(idx >> 12);
    int b   = row >> 6;
    int p   = row & 63;
    int pr  = p >> 3, pc = p & 7;
    int r   = d >> 8;
    int c   = (d >> 4) & 15;
    int ch  = d & 15;
    int H = pr * 16 + r;
    int W = pc * 16 + c;
    float v = 0.0f;
    if (H >= 1 && H <= 126 && W >= 1 && W <= 126)
        v = pool2[((long)(b * 126 + (H - 1)) * 126 + (W - 1)) * 16 + ch];
    patches[idx] = v;
}

// ---------------- TF32 tensor-core GEMM, cp.async 3-stage, 2 CTA/SM ---------
// C = A(MxK) * B(KxN) + bias (+relu).  BM=128, BN=128, BK=32.
// 256 threads = 8 warps (4 m x 2 n), warp tile 32x64 via m16n8k8.
// blockIdx.z = mat * splitk + kz.
// splitk>1: raw partials to part + z*M*N (no bias).  Requires nkt >= 2.

__device__ __forceinline__ void mma_tf32(float* d, const uint32_t* a, const uint32_t* b) {
    asm volatile(
        "mma.sync.aligned.m16n8k8.row.col.f32.tf32.tf32.f32 "
        "{%0,%1,%2,%3}, {%4,%5,%6,%7}, {%8,%9}, {%0,%1,%2,%3};\n"
        : "+f"(d[0]), "+f"(d[1]), "+f"(d[2]), "+f"(d[3])
        : "r"(a[0]), "r"(a[1]), "r"(a[2]), "r"(a[3]), "r"(b[0]), "r"(b[1]));
}

__device__ __forceinline__ void cp16s(uint32_t saddr, const void* gsrc) {
    asm volatile("cp.async.cg.shared.global [%0], [%1], 16;\n" :: "r"(saddr), "l"(gsrc));
}
__device__ __forceinline__ void cp_commit() { asm volatile("cp.async.commit_group;\n"); }
template <int N> __device__ __forceinline__ void cp_wait() {
    asm volatile("cp.async.wait_group %0;\n" :: "n"(N));
}

#define ASTR 36
#define BSTR 136
#define AS_TILE (128 * ASTR)
#define BS_TILE (32 * BSTR)
#define STAGE_U32 (AS_TILE + BS_TILE)
#define NSTAGE 3
#define GEMM_SMEM (NSTAGE * STAGE_U32 * 4)       // 107520 B -> 2 CTA/SM

__global__ __launch_bounds__(256, 2) void gemm_tf32_kernel(
    const float* __restrict__ A,
    const float* __restrict__ Bp0, const float* __restrict__ Bp1, const float* __restrict__ Bp2,
    const float* __restrict__ bi0, const float* __restrict__ bi1, const float* __restrict__ bi2,
    float* __restrict__ Cp0, float* __restrict__ Cp1, float* __restrict__ Cp2,
    float* __restrict__ part,
    int M, int N, int K, int splitk, int relu)
{
    extern __shared__ uint32_t smu[];

    const int z   = blockIdx.z;
    const int mat = z / splitk;
    const int kz  = z - mat * splitk;
    const float* B  = mat == 0 ? Bp0 : (mat == 1 ? Bp1 : Bp2);
    const float* bi = mat == 0 ? bi0 : (mat == 1 ? bi1 : bi2);
    float*       C  = mat == 0 ? Cp0 : (mat == 1 ? Cp1 : Cp2);

    const int tid  = threadIdx.x;
    const int lane = tid & 31;
    const int warp = tid >> 5;
    const int wm   = warp & 3;
    const int wn   = warp >> 2;
    const int gid  = lane >> 2;
    const int tkc  = lane & 3;

    const int bm = blockIdx.y * 128;
    const int bn = blockIdx.x * 128;

    const int ktot = K >> 5;
    const int ktb  = (kz * ktot) / splitk;
    const int kte  = ((kz + 1) * ktot) / splitk;
    const int nkt  = kte - ktb;

    const int rowA = tid >> 3;
    const int segA = (tid & 7) * 4;
    const int rowB = tid >> 5;
    const int segB = (tid & 31) * 4;
    const float* pA = A + (long)(bm + rowA) * K + ktb * 32 + segA;
    const float* pB = B + (long)(ktb * 32 + rowB) * N + bn + segB;
    const uint32_t sbase = (uint32_t)__cvta_generic_to_shared(smu);
    const uint32_t sA = sbase + (rowA * ASTR + segA) * 4;
    const uint32_t sB = sbase + (AS_TILE + rowB * BSTR + segB) * 4;

    auto issue = [&](int i) {
        const uint32_t off = (uint32_t)((i % NSTAGE) * STAGE_U32 * 4);
        const long kf = (long)i * 32;
#pragma unroll
        for (int t = 0; t < 4; t++)
            cp16s(sA + off + t * (32 * ASTR * 4), pA + t * 32 * (long)K + kf);
#pragma unroll
        for (int t = 0; t < 4; t++)
            cp16s(sB + off + t * (8 * BSTR * 4), pB + (kf + t * 8) * (long)N);
    };

    issue(0); cp_commit();
    if (nkt > 1) { issue(1); }
    cp_commit();

    float acc[2][8][4];
#pragma unroll
    for (int mc = 0; mc < 2; mc++)
#pragma unroll
        for (int nc = 0; nc < 8; nc++)
#pragma unroll
            for (int i = 0; i < 4; i++) acc[mc][nc][i] = 0.0f;

    for (int i = 0; i < nkt; i++) {
        cp_wait<1>();
        __syncthreads();
        if (i + 2 < nkt) issue(i + 2);
        cp_commit();

        const uint32_t* as = smu + (i % NSTAGE) * STAGE_U32;
        const uint32_t* bs = as + AS_TILE;

#pragma unroll
        for (int ks = 0; ks < 4; ks++) {
            const int kc = ks * 8 + tkc;
            uint32_t af[2][4];
#pragma unroll
            for (int mc = 0; mc < 2; mc++) {
                const int r = wm * 32 + mc * 16 + gid;
                af[mc][0] = as[r * ASTR + kc];
                af[mc][1] = as[(r + 8) * ASTR + kc];
                af[mc][2] = as[r * ASTR + kc + 4];
                af[mc][3] = as[(r + 8) * ASTR + kc + 4];
            }
#pragma unroll
            for (int nc = 0; nc < 8; nc++) {
                uint32_t bf[2];
                const int c = wn * 64 + nc * 8 + gid;
                bf[0] = bs[kc * BSTR + c];
                bf[1] = bs[(kc + 4) * BSTR + c];
                mma_tf32(acc[0][nc], af[0], bf);
                mma_tf32(acc[1][nc], af[1], bf);
            }
        }
    }

    if (splitk == 1) {
#pragma unroll
        for (int mc = 0; mc < 2; mc++) {
            const int r0 = bm + wm * 32 + mc * 16 + gid;
#pragma unroll
            for (int nc = 0; nc < 8; nc++) {
                const int col = bn + wn * 64 + nc * 8 + 2 * tkc;
                const float b0 = bi[col], b1 = bi[col + 1];
                float v0 = acc[mc][nc][0] + b0;
                float v1 = acc[mc][nc][1] + b1;
                float v2 = acc[mc][nc][2] + b0;
                float v3 = acc[mc][nc][3] + b1;
                if (relu) {
                    v0 = fmaxf(v0, 0.f); v1 = fmaxf(v1, 0.f);
                    v2 = fmaxf(v2, 0.f); v3 = fmaxf(v3, 0.f);
                }
                *(float2*)&C[(long)r0 * N + col]       = make_float2(v0, v1);
                *(float2*)&C[(long)(r0 + 8) * N + col] = make_float2(v2, v3);
            }
        }
    } else {
        float* P0 = part + (long)z * M * N;   // z includes mat for multi-mat splitk
#pragma unroll
        for (int mc = 0; mc < 2; mc++) {
            const int r0 = bm + wm * 32 + mc * 16 + gid;
#pragma unroll
            for (int nc = 0; nc < 8; nc++) {
                const int col = bn + wn * 64 + nc * 8 + 2 * tkc;
                *(float2*)&P0[(long)r0 * N + col]       = make_float2(acc[mc][nc][0], acc[mc][nc][1]);
                *(float2*)&P0[(long)(r0 + 8) * N + col] = make_float2(acc[mc][nc][2], acc[mc][nc][3]);
            }
        }
    }
}

// ordered, deterministic split-K reduce + bias (+relu)
__global__ void splitk_reduce_kernel(const float* __restrict__ part,
                                     const float* __restrict__ bias,
                                     float* __restrict__ C,
                                     int MN, int N, int splitk, int relu) {
    int idx = blockIdx.x * 256 + threadIdx.x;
    if (idx >= MN) return;
    float s = part[idx];
    for (int zz = 1; zz < splitk; zz++) s += part[(long)zz * MN + idx];
    s += bias[idx % N];
    if (relu) s = fmaxf(s, 0.0f);
    C[idx] = s;
}

// ---- attention with fused QKV split-K reduce --------------------------------
// part layout: z = mat*2 + kz; q:0,1  k:2,3  v:4,5 ; each slice MN = ROWSM*EDIM
__global__ void attn_sk_kernel(const float* __restrict__ part,
                               const float* __restrict__ bq,
                               const float* __restrict__ bk,
                               const float* __restrict__ bv,
                               float* __restrict__ O) {
    extern __shared__ float sm[];
    float* qs = sm;
    float* ks = qs + 64 * 65;
    float* vs = ks + 64 * 65;
    float* ss = vs + 64 * 65;

    const int MN = ROWSM * EDIM;
    int h = blockIdx.x;
    int b = blockIdx.y;
    int tid = threadIdx.x;

    for (int e = tid; e < 4096; e += 256) {
        int s = e >> 6, d = e & 63;
        int col = h * 64 + d;
        long base = ((long)(b * 64 + s) * EDIM) + col;
        qs[s * 65 + d] = part[base]          + part[MN + base]     + bq[col];
        ks[s * 65 + d] = part[2L * MN + base] + part[3L * MN + base] + bk[col];
        vs[s * 65 + d] = part[4L * MN + base] + part[5L * MN + base] + bv[col];
    }
    __syncthreads();

    for (int e = tid; e < 4096; e += 256) {
        int row = e >> 6, col = e & 63;
        float sum = 0.0f;
#pragma unroll 16
        for (int dd = 0; dd < 64; dd++)
            sum += qs[row * 65 + dd] * ks[col * 65 + dd];
        ss[row * 65 + col] = sum * 0.125f;
    }
    __syncthreads();

    if (tid < 64) {
        float* r = ss + tid * 65;
        float m = r[0];
#pragma unroll 16
        for (int c = 1; c < 64; c++) m = fmaxf(m, r[c]);
        float sum = 0.0f;
#pragma unroll 16
        for (int c = 0; c < 64; c++) { float e = expf(r[c] - m); r[c] = e; sum += e; }
        float inv = 1.0f / sum;
#pragma unroll 16
        for (int c = 0; c < 64; c++) r[c] *= inv;
    }
    __syncthreads();

    for (int e = tid; e < 4096; e += 256) {
        int row = e >> 6, d = e & 63;
        float sum = 0.0f;
#pragma unroll 16
        for (int col = 0; col < 64; col++)
            sum += ss[row * 65 + col] * vs[col * 65 + d];
        O[(long)b * (NHEADS * SEQ * HD) + h * 4096 + row * 64 + d] = sum;
    }
}

// ------ fused: y = 3 splitk partials + gemm bias; out = LN(x + y) -----------
__global__ void add_ln_splitk_kernel(const float* __restrict__ x,
                                     const float* __restrict__ part,
                                     const float* __restrict__ gb,
                                     const float* __restrict__ g,
                                     const float* __restrict__ be,
                                     float* __restrict__ out,
                                     int MN) {
    __shared__ float buf[EDIM];
    __shared__ float red[256];
    int row = blockIdx.x;
    int tid = threadIdx.x;
    long base = (long)row * EDIM;

    float partial = 0.0f;
    for (int e = tid; e < EDIM; e += 256) {
        float y = part[base + e] + part[MN + base + e] + part[2L * MN + base + e] + gb[e];
        float v = x[base + e] + y;
        buf[e] = v;
        partial += v;
    }
    red[tid] = partial;
    __syncthreads();
    for (int s = 128; s > 0; s >>= 1) {
        if (tid < s) red[tid] += red[tid + s];
        __syncthreads();
    }
    float mean = red[0] * (1.0f / EDIM);
    __syncthreads();

    float p2 = 0.0f;
    for (int e = tid; e < EDIM; e += 256) {
        float d = buf[e] - mean;
        p2 += d * d;
    }
    red[tid] = p2;
    __syncthreads();
    for (int s = 128; s > 0; s >>= 1) {
        if (tid < s) red[tid] += red[tid + s];
        __syncthreads();
    }
    float var = red[0] * (1.0f / EDIM);
    float rstd = rsqrtf(var + 1e-6f);

    for (int e = tid; e < EDIM; e += 256)
        out[base + e] = (buf[e] - mean) * rstd * g[e] + be[e];
}

// ---------------- mean-pool + head + sigmoid --------------------------------
__global__ void head_kernel(const float* __restrict__ t,
                            const float* __restrict__ hw,
                            const float* __restrict__ hb,
                            float* __restrict__ out) {
    __shared__ float red[256];
    int b = blockIdx.x;
    int tid = threadIdx.x;
    float partial = 0.0f;
    for (int e = tid; e < EDIM; e += 256) {
        float se = 0.0f;
        for (int s = 0; s < SEQ; s++)
            se += t[((long)(b * SEQ + s)) * EDIM + e];
        partial += (se * (1.0f / SEQ)) * hw[e];
    }
    red[tid] = partial;
    __syncthreads();
    for (int s = 128; s > 0; s >>= 1) {
        if (tid < s) red[tid] += red[tid + s];
        __syncthreads();
    }
    if (tid == 0) {
        float z = red[0] + hb[0];
        out[b] = 1.0f / (1.0f + expf(-z));
    }
}

// ---------------- host launch ------------------------------------------------
static inline void launch_gemm(const float* A, const float* B, const float* bias,
                               float* C, float* part,
                               int M, int N, int K, int splitk, int relu,
                               int do_reduce) {
    dim3 grid(N / 128, M / 128, splitk);
    gemm_tf32_kernel<<<grid, 256, GEMM_SMEM>>>(A, B, B, B, bias, bias, bias,
                                               C, C, C, part, M, N, K, splitk, relu);
    if (splitk > 1 && do_reduce) {
        int MN = M * N;
        splitk_reduce_kernel<<<(MN + 255) / 256, 256>>>(part, bias, C, MN, N, splitk, relu);
    }
}

extern "C" void kernel_launch(void* const* d_in, const int* in_sizes, int n_in,
                              void* d_out, int out_size) {
    const float* x       = (const float*)d_in[0];
    const float* conv1_w = (const float*)d_in[1];
    const float* conv1_b = (const float*)d_in[2];
    const float* conv2_w = (const float*)d_in[3];
    const float* conv2_b = (const float*)d_in[4];
    const float* proj_w  = (const float*)d_in[5];
    const float* proj_b  = (const float*)d_in[6];
    const float* Wq = (const float*)d_in[7];
    const float* bq = (const float*)d_in[8];
    const float* Wk = (const float*)d_in[9];
    const float* bk = (const float*)d_in[10];
    const float* Wv = (const float*)d_in[11];
    const float* bv = (const float*)d_in[12];
    const float* Wo = (const float*)d_in[13];
    const float* bo = (const float*)d_in[14];
    const float* W1 = (const float*)d_in[15];
    const float* b1 = (const float*)d_in[16];
    const float* W2 = (const float*)d_in[17];
    const float* b2 = (const float*)d_in[18];
    const float* ln1_g = (const float*)d_in[19];
    const float* ln1_b = (const float*)d_in[20];
    const float* ln2_g = (const float*)d_in[21];
    const float* ln2_b = (const float*)d_in[22];
    const float* head_w = (const float*)d_in[23];
    const float* head_b = (const float*)d_in[24];
    float* out = (float*)d_out;

    float *pool1, *pool2, *patches, *t, *q, *k, *v, *att, *o1, *f1, *f2, *part;
    cudaGetSymbolAddress((void**)&pool1, g_pool1);
    cudaGetSymbolAddress((void**)&pool2, g_pool2);
    cudaGetSymbolAddress((void**)&patches, g_patches);
    cudaGetSymbolAddress((void**)&t,  g_t);
    cudaGetSymbolAddress((void**)&q,  g_q);
    cudaGetSymbolAddress((void**)&k,  g_k);
    cudaGetSymbolAddress((void**)&v,  g_v);
    cudaGetSymbolAddress((void**)&att, g_att);
    cudaGetSymbolAddress((void**)&o1, g_o1);
    cudaGetSymbolAddress((void**)&f1, g_f1);
    cudaGetSymbolAddress((void**)&f2, g_f2);
    cudaGetSymbolAddress((void**)&part, g_part);

    const int attn_smem = 4 * 64 * 65 * sizeof(float);
    cudaFuncSetAttribute(attn_sk_kernel, cudaFuncAttributeMaxDynamicSharedMemorySize, attn_smem);
    cudaFuncSetAttribute(gemm_tf32_kernel, cudaFuncAttributeMaxDynamicSharedMemorySize, GEMM_SMEM);

    // conv stack
    {
        int n1 = 16 * 255 * 255;
        conv1_pool_kernel<<<(n1 + 255) / 256, 256>>>(x, conv1_w, conv1_b, pool1);
        int n2 = 16 * 126 * 126;
        conv2_pool_kernel<<<(n2 + 255) / 256, 256>>>(pool1, conv2_w, conv2_b, pool2);
        long np = (long)ROWSM * PDIM;
        patch_kernel<<<(int)((np + 255) / 256), 256>>>(pool2, patches);
    }

    // patch projection (K=4096, splitk=6 -> 288 blocks)
    launch_gemm(patches, proj_w, proj_b, t, part, ROWSM, EDIM, PDIM, 6, 0, 1);

    const int MN_E = ROWSM * EDIM;

    for (int i = 0; i < NLAYER; i++) {
        const float* wq = Wq + (long)i * EDIM * EDIM;
        const float* wk = Wk + (long)i * EDIM * EDIM;
        const float* wv = Wv + (long)i * EDIM * EDIM;
        const float* wo = Wo + (long)i * EDIM * EDIM;
        const float* w1 = W1 + (long)i * EDIM * FFDIM;
        const float* w2 = W2 + (long)i * FFDIM * EDIM;

        // fused QKV: splitk=2 per matrix -> 6x8x6 = 288 blocks (2 CTA/SM wave);
        // partials reduced inside attn_sk_kernel.
        {
            dim3 grid(EDIM / 128, ROWSM / 128, 6);
            gemm_tf32_kernel<<<grid, 256, GEMM_SMEM>>>(
                t, wq, wk, wv,
                bq + i * EDIM, bk + i * EDIM, bv + i * EDIM,
                q, k, v, part, ROWSM, EDIM, EDIM, 2, 0);
        }

        attn_sk_kernel<<<dim3(NHEADS, BB), 256, attn_smem>>>(
            part, bq + i * EDIM, bk + i * EDIM, bv + i * EDIM, att);

        // Wo (splitk=3 -> 288 blocks, reduce fused into add+LN)
        launch_gemm(att, wo, bo + i * EDIM, NULL, part, ROWSM, EDIM, EDIM, 3, 0, 0);
        add_ln_splitk_kernel<<<ROWSM, 256>>>(t, part, bo + i * EDIM,
                                             ln1_g + i * EDIM, ln1_b + i * EDIM, o1, MN_E);

        // FF1 (splitk=3 -> 576 blocks, relu reduce)
        launch_gemm(o1, w1, b1 + i * FFDIM, f1, part, ROWSM, FFDIM, EDIM, 3, 1, 1);

        // FF2 (splitk=3 -> 288 blocks, reduce fused into add+LN)
        launch_gemm(f1, w2, b2 + i * EDIM, NULL, part, ROWSM, EDIM, FFDIM, 3, 0, 0);
        add_ln_splitk_kernel<<<ROWSM, 256>>>(o1, part, b2 + i * EDIM,
                                             ln2_g + i * EDIM, ln2_b + i * EDIM, t, MN_E);
    }

    head_kernel<<<BB, 256>>>(t, head_w, head_b, out);
}

// round 7
// speedup vs baseline: 1.1204x; 1.1204x over previous
#include <cuda_runtime.h>
#include <cuda_fp16.h>
#include <math.h>
#include <stdint.h>

// ---------------- model constants ----------------
#define BB     16
#define EDIM   768
#define NHEADS 12
#define HD     64
#define FFDIM  3072
#define NLAYER 8
#define SEQ    64
#define ROWSM  1024     // BB*SEQ
#define PDIM   4096

// ---------------- scratch (device globals) ----------------
__device__ float g_pool1[16 * 255 * 255 * 16];
__device__ float g_pool2[16 * 126 * 126 * 16];
__device__ float g_t [ROWSM * EDIM];
__device__ float g_q [ROWSM * EDIM];
__device__ float g_k [ROWSM * EDIM];
__device__ float g_v [ROWSM * EDIM];
__device__ float g_o1[ROWSM * EDIM];
__device__ float g_part[3 * ROWSM * FFDIM];          // split-K fp32 partials

// fp16 packed-pair (u32 = 2 halves along K) buffers
__device__ uint32_t g_patch16[ROWSM * PDIM / 2];
__device__ uint32_t g_t16  [ROWSM * EDIM / 2];
__device__ uint32_t g_att16[ROWSM * EDIM / 2];
__device__ uint32_t g_o116 [ROWSM * EDIM / 2];
__device__ uint32_t g_f116 [ROWSM * FFDIM / 2];
// converted weights: [K/2][N] u32, pair = (k, k+1) at fixed n
__device__ uint32_t g_wq16[NLAYER * EDIM * EDIM / 2];
__device__ uint32_t g_wk16[NLAYER * EDIM * EDIM / 2];
__device__ uint32_t g_wv16[NLAYER * EDIM * EDIM / 2];
__device__ uint32_t g_wo16[NLAYER * EDIM * EDIM / 2];
__device__ uint32_t g_w116[NLAYER * EDIM * FFDIM / 2];
__device__ uint32_t g_w216[NLAYER * FFDIM * EDIM / 2];
__device__ uint32_t g_wp16[PDIM * EDIM / 2];

// ---------------- weight conversion: [K][N] fp32 -> [K/2][N] u32 ------------
__global__ void cvt_w_kernel(const float* __restrict__ W, uint32_t* __restrict__ O,
                             long total, int N) {
    long idx = (long)blockIdx.x * 256 + threadIdx.x;
    if (idx >= total) return;
    long kp = idx / N;
    int  n  = (int)(idx - kp * N);
    float a = W[(2 * kp) * (long)N + n];
    float b = W[(2 * kp + 1) * (long)N + n];
    __half2 h = __floats2half2_rn(a, b);
    O[idx] = *(uint32_t*)&h;
}

// ---------------- conv1 + relu + maxpool --------------------------------
__global__ void conv1_pool_kernel(const float* __restrict__ x,
                                  const float* __restrict__ w,
                                  const float* __restrict__ bias,
                                  float* __restrict__ out) {
    __shared__ float ws[432];
    __shared__ float bs[16];
    int tid = threadIdx.x;
    for (int i = tid; i < 432; i += 256) ws[i] = w[i];
    if (tid < 16) bs[tid] = bias[tid];
    __syncthreads();

    int idx = blockIdx.x * 256 + tid;
    if (idx >= 16 * 255 * 255) return;
    int pw = idx % 255;
    int t  = idx / 255;
    int ph = t % 255;
    int b  = t / 255;

    float mx[16];
#pragma unroll
    for (int c = 0; c < 16; c++) mx[c] = 0.0f;

    for (int dy = 0; dy < 2; dy++) {
        for (int dx = 0; dx < 2; dx++) {
            int h0 = 2 * ph + dy;
            int w0 = 2 * pw + dx;
            float acc[16];
#pragma unroll
            for (int c = 0; c < 16; c++) acc[c] = bs[c];
            for (int kh = 0; kh < 3; kh++) {
                for (int kw = 0; kw < 3; kw++) {
                    const float* xp = x + (((long)(b * 512 + h0 + kh) * 512) + (w0 + kw)) * 3;
                    float x0 = xp[0], x1 = xp[1], x2 = xp[2];
                    const float* wp = ws + ((kh * 3 + kw) * 3) * 16;
#pragma unroll
                    for (int c = 0; c < 16; c++)
                        acc[c] += x0 * wp[c] + x1 * wp[16 + c] + x2 * wp[32 + c];
                }
            }
#pragma unroll
            for (int c = 0; c < 16; c++) mx[c] = fmaxf(mx[c], fmaxf(acc[c], 0.0f));
        }
    }
    float* op = out + (long)idx * 16;
#pragma unroll
    for (int c = 0; c < 16; c++) op[c] = mx[c];
}

// ---------------- conv2 + relu + maxpool --------------------------------
__global__ void conv2_pool_kernel(const float* __restrict__ in,
                                  const float* __restrict__ w,
                                  const float* __restrict__ bias,
                                  float* __restrict__ out) {
    __shared__ float ws[2304];
    __shared__ float bs[16];
    int tid = threadIdx.x;
    for (int i = tid; i < 2304; i += 256) ws[i] = w[i];
    if (tid < 16) bs[tid] = bias[tid];
    __syncthreads();

    int idx = blockIdx.x * 256 + tid;
    if (idx >= 16 * 126 * 126) return;
    int pw = idx % 126;
    int t  = idx / 126;
    int ph = t % 126;
    int b  = t / 126;

    float mx[16];
#pragma unroll
    for (int c = 0; c < 16; c++) mx[c] = 0.0f;

    for (int dy = 0; dy < 2; dy++) {
        for (int dx = 0; dx < 2; dx++) {
            int h0 = 2 * ph + dy;
            int w0 = 2 * pw + dx;
            float acc[16];
#pragma unroll
            for (int c = 0; c < 16; c++) acc[c] = bs[c];
            for (int kh = 0; kh < 3; kh++) {
                for (int kw = 0; kw < 3; kw++) {
                    const float* xp = in + ((long)(b * 255 + h0 + kh) * 255 + (w0 + kw)) * 16;
                    float xv[16];
#pragma unroll
                    for (int ci = 0; ci < 16; ci++) xv[ci] = xp[ci];
                    const float* wp = ws + ((kh * 3 + kw) * 16) * 16;
#pragma unroll
                    for (int ci = 0; ci < 16; ci++) {
#pragma unroll
                        for (int c = 0; c < 16; c++)
                            acc[c] += xv[ci] * wp[ci * 16 + c];
                    }
                }
            }
#pragma unroll
            for (int c = 0; c < 16; c++) mx[c] = fmaxf(mx[c], fmaxf(acc[c], 0.0f));
        }
    }
    float* op = out + (long)idx * 16;
#pragma unroll
    for (int c = 0; c < 16; c++) op[c] = mx[c];
}

// ---------------- patch gather -> fp16 ---------------------------------------
__global__ void patch_kernel(const float* __restrict__ pool2,
                             __half* __restrict__ patches16) {
    long idx = (long)blockIdx.x * 256 + threadIdx.x;
    if (idx >= (long)ROWSM * PDIM) return;
    int d   = (int)(idx & (PDIM - 1));
    int row = (int)(idx >> 12);
    int b   = row >> 6;
    int p   = row & 63;
    int pr  = p >> 3, pc = p & 7;
    int r   = d >> 8;
    int c   = (d >> 4) & 15;
    int ch  = d & 15;
    int H = pr * 16 + r;
    int W = pc * 16 + c;
    float v = 0.0f;
    if (H >= 1 && H <= 126 && W >= 1 && W <= 126)
        v = pool2[((long)(b * 126 + (H - 1)) * 126 + (W - 1)) * 16 + ch];
    patches16[idx] = __float2half(v);
}

// ---------------- FP16 tensor-core GEMM, cp.async 3-stage --------------------
// C = A(MxK,fp16 pairs) * B(KxN,fp16 pairs) + bias (+relu).  BM=128,BN=128,BK=64.
// 256 threads = 8 warps (4m x 2n), warp tile 32x64 via m16n8k16.f16 (fp32 acc).
// blockIdx.z = mat * splitk + kz.  splitk>1: raw fp32 partials to part + z*M*N.
// Requires nkt >= 2.

__device__ __forceinline__ void mma_f16(float* d, const uint32_t* a, const uint32_t* b) {
    asm volatile(
        "mma.sync.aligned.m16n8k16.row.col.f32.f16.f16.f32 "
        "{%0,%1,%2,%3}, {%4,%5,%6,%7}, {%8,%9}, {%0,%1,%2,%3};\n"
        : "+f"(d[0]), "+f"(d[1]), "+f"(d[2]), "+f"(d[3])
        : "r"(a[0]), "r"(a[1]), "r"(a[2]), "r"(a[3]), "r"(b[0]), "r"(b[1]));
}

__device__ __forceinline__ void cp16s(uint32_t saddr, const void* gsrc) {
    asm volatile("cp.async.cg.shared.global [%0], [%1], 16;\n" :: "r"(saddr), "l"(gsrc));
}
__device__ __forceinline__ void cp_commit() { asm volatile("cp.async.commit_group;\n"); }
template <int N> __device__ __forceinline__ void cp_wait() {
    asm volatile("cp.async.wait_group %0;\n" :: "n"(N));
}

#define ASTR 36                  // u32 per A row: 32 data (64 fp16) + 4 pad
#define BSTR 136                 // u32 per B kp-row: 128 data + 8 pad
#define AS_TILE (128 * ASTR)
#define BS_TILE (32 * BSTR)
#define STAGE_U32 (AS_TILE + BS_TILE)
#define NSTAGE 3
#define GEMM_SMEM (NSTAGE * STAGE_U32 * 4)   // 107520 B

__global__ __launch_bounds__(256, 2) void gemm_f16_kernel(
    const uint32_t* __restrict__ A,       // [M][K/2] u32
    const uint32_t* __restrict__ Bp0, const uint32_t* __restrict__ Bp1,
    const uint32_t* __restrict__ Bp2,     // [K/2][N] u32
    const float* __restrict__ bi0, const float* __restrict__ bi1,
    const float* __restrict__ bi2,
    float* __restrict__ Cp0, float* __restrict__ Cp1, float* __restrict__ Cp2,
    float* __restrict__ part,
    int M, int N, int K, int splitk, int relu)
{
    extern __shared__ uint32_t smu[];

    const int z   = blockIdx.z;
    const int mat = z / splitk;
    const int kz  = z - mat * splitk;
    const uint32_t* B  = mat == 0 ? Bp0 : (mat == 1 ? Bp1 : Bp2);
    const float*    bi = mat == 0 ? bi0 : (mat == 1 ? bi1 : bi2);
    float*          C  = mat == 0 ? Cp0 : (mat == 1 ? Cp1 : Cp2);

    const int tid  = threadIdx.x;
    const int lane = tid & 31;
    const int warp = tid >> 5;
    const int wm   = warp & 3;
    const int wn   = warp >> 2;
    const int gid  = lane >> 2;
    const int tkc  = lane & 3;

    const int bm = blockIdx.y * 128;
    const int bn = blockIdx.x * 128;

    const int KP   = K >> 1;          // u32 per A row
    const int ktot = K >> 6;          // kblks of 64
    const int ktb  = (kz * ktot) / splitk;
    const int kte  = ((kz + 1) * ktot) / splitk;
    const int nkt  = kte - ktb;

    const int rowA = tid >> 3;            // 0..31 (+32 per rep)
    const int segA = (tid & 7) * 4;       // u32
    const int rowB = tid >> 5;            // 0..7 (+8 per rep)
    const int segB = (tid & 31) * 4;      // u32
    const uint32_t* pA = A + (long)(bm + rowA) * KP + ktb * 32 + segA;
    const uint32_t* pB = B + (long)(ktb * 32 + rowB) * N + bn + segB;
    const uint32_t sbase = (uint32_t)__cvta_generic_to_shared(smu);
    const uint32_t sA = sbase + (rowA * ASTR + segA) * 4;
    const uint32_t sB = sbase + (AS_TILE + rowB * BSTR + segB) * 4;

    auto issue = [&](int i) {
        const uint32_t off = (uint32_t)((i % NSTAGE) * STAGE_U32 * 4);
        const long kf = (long)i * 32;     // u32 along k
#pragma unroll
        for (int t = 0; t < 4; t++)
            cp16s(sA + off + t * (32 * ASTR * 4), pA + t * 32 * (long)KP + kf);
#pragma unroll
        for (int t = 0; t < 4; t++)
            cp16s(sB + off + t * (8 * BSTR * 4), pB + (kf + t * 8) * (long)N);
    };

    issue(0); cp_commit();
    if (nkt > 1) { issue(1); }
    cp_commit();

    float acc[2][8][4];
#pragma unroll
    for (int mc = 0; mc < 2; mc++)
#pragma unroll
        for (int nc = 0; nc < 8; nc++)
#pragma unroll
            for (int i = 0; i < 4; i++) acc[mc][nc][i] = 0.0f;

    for (int i = 0; i < nkt; i++) {
        cp_wait<1>();
        __syncthreads();
        if (i + 2 < nkt) issue(i + 2);
        cp_commit();

        const uint32_t* as = smu + (i % NSTAGE) * STAGE_U32;
        const uint32_t* bs = as + AS_TILE;

#pragma unroll
        for (int ks = 0; ks < 4; ks++) {
            const int kc = ks * 8 + tkc;          // u32 (k-pair) index
            uint32_t af[2][4];
#pragma unroll
            for (int mc = 0; mc < 2; mc++) {
                const int r = wm * 32 + mc * 16 + gid;
                af[mc][0] = as[r * ASTR + kc];
                af[mc][1] = as[(r + 8) * ASTR + kc];
                af[mc][2] = as[r * ASTR + kc + 4];
                af[mc][3] = as[(r + 8) * ASTR + kc + 4];
            }
#pragma unroll
            for (int nc = 0; nc < 8; nc++) {
                uint32_t bf[2];
                const int c = wn * 64 + nc * 8 + gid;
                bf[0] = bs[kc * BSTR + c];
                bf[1] = bs[(kc + 4) * BSTR + c];
                mma_f16(acc[0][nc], af[0], bf);
                mma_f16(acc[1][nc], af[1], bf);
            }
        }
    }

    if (splitk == 1) {
#pragma unroll
        for (int mc = 0; mc < 2; mc++) {
            const int r0 = bm + wm * 32 + mc * 16 + gid;
#pragma unroll
            for (int nc = 0; nc < 8; nc++) {
                const int col = bn + wn * 64 + nc * 8 + 2 * tkc;
                const float b0 = bi[col], b1 = bi[col + 1];
                float v0 = acc[mc][nc][0] + b0;
                float v1 = acc[mc][nc][1] + b1;
                float v2 = acc[mc][nc][2] + b0;
                float v3 = acc[mc][nc][3] + b1;
                if (relu) {
                    v0 = fmaxf(v0, 0.f); v1 = fmaxf(v1, 0.f);
                    v2 = fmaxf(v2, 0.f); v3 = fmaxf(v3, 0.f);
                }
                *(float2*)&C[(long)r0 * N + col]       = make_float2(v0, v1);
                *(float2*)&C[(long)(r0 + 8) * N + col] = make_float2(v2, v3);
            }
        }
    } else {
        float* P0 = part + (long)z * M * N;
#pragma unroll
        for (int mc = 0; mc < 2; mc++) {
            const int r0 = bm + wm * 32 + mc * 16 + gid;
#pragma unroll
            for (int nc = 0; nc < 8; nc++) {
                const int col = bn + wn * 64 + nc * 8 + 2 * tkc;
                *(float2*)&P0[(long)r0 * N + col]       = make_float2(acc[mc][nc][0], acc[mc][nc][1]);
                *(float2*)&P0[(long)(r0 + 8) * N + col] = make_float2(acc[mc][nc][2], acc[mc][nc][3]);
            }
        }
    }
}

// ordered split-K reduce + bias (+relu); optional fp32 and fp16 outputs
__global__ void splitk_reduce_kernel(const float* __restrict__ part,
                                     const float* __restrict__ bias,
                                     float* __restrict__ Cf,
                                     __half* __restrict__ Ch,
                                     int MN, int N, int splitk, int relu) {
    int idx = blockIdx.x * 256 + threadIdx.x;
    if (idx >= MN) return;
    float s = part[idx];
    for (int zz = 1; zz < splitk; zz++) s += part[(long)zz * MN + idx];
    s += bias[idx % N];
    if (relu) s = fmaxf(s, 0.0f);
    if (Cf) Cf[idx] = s;
    if (Ch) Ch[idx] = __float2half(s);
}

// ---------------- attention: one block per (b, head); fp16 output -----------
__global__ void attn_kernel(const float* __restrict__ Q,
                            const float* __restrict__ K,
                            const float* __restrict__ V,
                            __half* __restrict__ O16) {
    extern __shared__ float sm[];
    float* qs = sm;
    float* ks = qs + 64 * 65;
    float* vs = ks + 64 * 65;
    float* ss = vs + 64 * 65;

    int h = blockIdx.x;
    int b = blockIdx.y;
    int tid = threadIdx.x;

    for (int e = tid; e < 4096; e += 256) {
        int s = e >> 6, d = e & 63;
        long base = ((long)(b * 64 + s) * EDIM) + h * 64 + d;
        qs[s * 65 + d] = Q[base];
        ks[s * 65 + d] = K[base];
        vs[s * 65 + d] = V[base];
    }
    __syncthreads();

    for (int e = tid; e < 4096; e += 256) {
        int row = e >> 6, col = e & 63;
        float sum = 0.0f;
#pragma unroll 16
        for (int dd = 0; dd < 64; dd++)
            sum += qs[row * 65 + dd] * ks[col * 65 + dd];
        ss[row * 65 + col] = sum * 0.125f;
    }
    __syncthreads();

    if (tid < 64) {
        float* r = ss + tid * 65;
        float m = r[0];
#pragma unroll 16
        for (int c = 1; c < 64; c++) m = fmaxf(m, r[c]);
        float sum = 0.0f;
#pragma unroll 16
        for (int c = 0; c < 64; c++) { float e = expf(r[c] - m); r[c] = e; sum += e; }
        float inv = 1.0f / sum;
#pragma unroll 16
        for (int c = 0; c < 64; c++) r[c] *= inv;
    }
    __syncthreads();

    // out[b, h*4096 + row*64 + d]  (faithful reshape-without-transpose)
    for (int e = tid; e < 4096; e += 256) {
        int row = e >> 6, d = e & 63;
        float sum = 0.0f;
#pragma unroll 16
        for (int col = 0; col < 64; col++)
            sum += ss[row * 65 + col] * vs[col * 65 + d];
        O16[(long)b * (NHEADS * SEQ * HD) + h * 4096 + row * 64 + d] = __float2half(sum);
    }
}

// ------ fused: y = 3 splitk partials + bias; out = LN(x + y), fp32+fp16 -----
__global__ void add_ln_splitk_kernel(const float* __restrict__ x,
                                     const float* __restrict__ part,
                                     const float* __restrict__ gb,
                                     const float* __restrict__ g,
                                     const float* __restrict__ be,
                                     float* __restrict__ out,
                                     __half* __restrict__ out16,
                                     int MN) {
    __shared__ float buf[EDIM];
    __shared__ float red[256];
    int row = blockIdx.x;
    int tid = threadIdx.x;
    long base = (long)row * EDIM;

    float partial = 0.0f;
    for (int e = tid; e < EDIM; e += 256) {
        float y = part[base + e] + part[MN + base + e] + part[2L * MN + base + e] + gb[e];
        float v = x[base + e] + y;
        buf[e] = v;
        partial += v;
    }
    red[tid] = partial;
    __syncthreads();
    for (int s = 128; s > 0; s >>= 1) {
        if (tid < s) red[tid] += red[tid + s];
        __syncthreads();
    }
    float mean = red[0] * (1.0f / EDIM);
    __syncthreads();

    float p2 = 0.0f;
    for (int e = tid; e < EDIM; e += 256) {
        float d = buf[e] - mean;
        p2 += d * d;
    }
    red[tid] = p2;
    __syncthreads();
    for (int s = 128; s > 0; s >>= 1) {
        if (tid < s) red[tid] += red[tid + s];
        __syncthreads();
    }
    float var = red[0] * (1.0f / EDIM);
    float rstd = rsqrtf(var + 1e-6f);

    for (int e = tid; e < EDIM; e += 256) {
        float o = (buf[e] - mean) * rstd * g[e] + be[e];
        out[base + e] = o;
        out16[base + e] = __float2half(o);
    }
}

// ---------------- mean-pool + head + sigmoid --------------------------------
__global__ void head_kernel(const float* __restrict__ t,
                            const float* __restrict__ hw,
                            const float* __restrict__ hb,
                            float* __restrict__ out) {
    __shared__ float red[256];
    int b = blockIdx.x;
    int tid = threadIdx.x;
    float partial = 0.0f;
    for (int e = tid; e < EDIM; e += 256) {
        float se = 0.0f;
        for (int s = 0; s < SEQ; s++)
            se += t[((long)(b * SEQ + s)) * EDIM + e];
        partial += (se * (1.0f / SEQ)) * hw[e];
    }
    red[tid] = partial;
    __syncthreads();
    for (int s = 128; s > 0; s >>= 1) {
        if (tid < s) red[tid] += red[tid + s];
        __syncthreads();
    }
    if (tid == 0) {
        float z = red[0] + hb[0];
        out[b] = 1.0f / (1.0f + expf(-z));
    }
}

// ---------------- host launch ------------------------------------------------
static inline void launch_gemm(const uint32_t* A, const uint32_t* B, const float* bias,
                               float* C, float* part,
                               int M, int N, int K, int splitk, int relu) {
    dim3 grid(N / 128, M / 128, splitk);
    gemm_f16_kernel<<<grid, 256, GEMM_SMEM>>>(A, B, B, B, bias, bias, bias,
                                              C, C, C, part, M, N, K, splitk, relu);
}

static inline void launch_cvt(const float* W, uint32_t* O, long kp_total, int N) {
    long total = kp_total * N;
    cvt_w_kernel<<<(int)((total + 255) / 256), 256>>>(W, O, total, N);
}

extern "C" void kernel_launch(void* const* d_in, const int* in_sizes, int n_in,
                              void* d_out, int out_size) {
    const float* x       = (const float*)d_in[0];
    const float* conv1_w = (const float*)d_in[1];
    const float* conv1_b = (const float*)d_in[2];
    const float* conv2_w = (const float*)d_in[3];
    const float* conv2_b = (const float*)d_in[4];
    const float* proj_w  = (const float*)d_in[5];
    const float* proj_b  = (const float*)d_in[6];
    const float* Wq = (const float*)d_in[7];
    const float* bq = (const float*)d_in[8];
    const float* Wk = (const float*)d_in[9];
    const float* bk = (const float*)d_in[10];
    const float* Wv = (const float*)d_in[11];
    const float* bv = (const float*)d_in[12];
    const float* Wo = (const float*)d_in[13];
    const float* bo = (const float*)d_in[14];
    const float* W1 = (const float*)d_in[15];
    const float* b1 = (const float*)d_in[16];
    const float* W2 = (const float*)d_in[17];
    const float* b2 = (const float*)d_in[18];
    const float* ln1_g = (const float*)d_in[19];
    const float* ln1_b = (const float*)d_in[20];
    const float* ln2_g = (const float*)d_in[21];
    const float* ln2_b = (const float*)d_in[22];
    const float* head_w = (const float*)d_in[23];
    const float* head_b = (const float*)d_in[24];
    float* out = (float*)d_out;

    float *pool1, *pool2, *t, *q, *k, *v, *o1, *part;
    uint32_t *patch16, *t16, *att16, *o116, *f116;
    uint32_t *wq16, *wk16, *wv16, *wo16, *w116, *w216, *wp16;
    cudaGetSymbolAddress((void**)&pool1, g_pool1);
    cudaGetSymbolAddress((void**)&pool2, g_pool2);
    cudaGetSymbolAddress((void**)&t,  g_t);
    cudaGetSymbolAddress((void**)&q,  g_q);
    cudaGetSymbolAddress((void**)&k,  g_k);
    cudaGetSymbolAddress((void**)&v,  g_v);
    cudaGetSymbolAddress((void**)&o1, g_o1);
    cudaGetSymbolAddress((void**)&part, g_part);
    cudaGetSymbolAddress((void**)&patch16, g_patch16);
    cudaGetSymbolAddress((void**)&t16,  g_t16);
    cudaGetSymbolAddress((void**)&att16, g_att16);
    cudaGetSymbolAddress((void**)&o116, g_o116);
    cudaGetSymbolAddress((void**)&f116, g_f116);
    cudaGetSymbolAddress((void**)&wq16, g_wq16);
    cudaGetSymbolAddress((void**)&wk16, g_wk16);
    cudaGetSymbolAddress((void**)&wv16, g_wv16);
    cudaGetSymbolAddress((void**)&wo16, g_wo16);
    cudaGetSymbolAddress((void**)&w116, g_w116);
    cudaGetSymbolAddress((void**)&w216, g_w216);
    cudaGetSymbolAddress((void**)&wp16, g_wp16);

    const int attn_smem = 4 * 64 * 65 * sizeof(float);
    cudaFuncSetAttribute(attn_kernel, cudaFuncAttributeMaxDynamicSharedMemorySize, attn_smem);
    cudaFuncSetAttribute(gemm_f16_kernel, cudaFuncAttributeMaxDynamicSharedMemorySize, GEMM_SMEM);

    // weight conversion (fp32 -> packed fp16 pairs)
    launch_cvt(proj_w, wp16, PDIM / 2, EDIM);
    launch_cvt(Wq, wq16, (long)NLAYER * EDIM / 2, EDIM);
    launch_cvt(Wk, wk16, (long)NLAYER * EDIM / 2, EDIM);
    launch_cvt(Wv, wv16, (long)NLAYER * EDIM / 2, EDIM);
    launch_cvt(Wo, wo16, (long)NLAYER * EDIM / 2, EDIM);
    launch_cvt(W1, w116, (long)NLAYER * EDIM / 2, FFDIM);
    launch_cvt(W2, w216, (long)NLAYER * FFDIM / 2, EDIM);

    // conv stack
    {
        int n1 = 16 * 255 * 255;
        conv1_pool_kernel<<<(n1 + 255) / 256, 256>>>(x, conv1_w, conv1_b, pool1);
        int n2 = 16 * 126 * 126;
        conv2_pool_kernel<<<(n2 + 255) / 256, 256>>>(pool1, conv2_w, conv2_b, pool2);
        long np = (long)ROWSM * PDIM;
        patch_kernel<<<(int)((np + 255) / 256), 256>>>(pool2, (__half*)patch16);
    }

    const int MN_E = ROWSM * EDIM;

    // patch projection (K=4096, splitk=3)
    launch_gemm(patch16, wp16, proj_b, NULL, part, ROWSM, EDIM, PDIM, 3, 0);
    splitk_reduce_kernel<<<(MN_E + 255) / 256, 256>>>(part, proj_b, t, (__half*)t16,
                                                      MN_E, EDIM, 3, 0);

    for (int i = 0; i < NLAYER; i++) {
        const uint32_t* wq = wq16 + (long)i * EDIM * EDIM / 2;
        const uint32_t* wk = wk16 + (long)i * EDIM * EDIM / 2;
        const uint32_t* wv = wv16 + (long)i * EDIM * EDIM / 2;
        const uint32_t* wo = wo16 + (long)i * EDIM * EDIM / 2;
        const uint32_t* w1 = w116 + (long)i * EDIM * FFDIM / 2;
        const uint32_t* w2 = w216 + (long)i * FFDIM * EDIM / 2;

        // fused QKV: z = 3 matrices
        {
            dim3 grid(EDIM / 128, ROWSM / 128, 3);
            gemm_f16_kernel<<<grid, 256, GEMM_SMEM>>>(
                t16, wq, wk, wv,
                bq + i * EDIM, bk + i * EDIM, bv + i * EDIM,
                q, k, v, part, ROWSM, EDIM, EDIM, 1, 0);
        }

        attn_kernel<<<dim3(NHEADS, BB), 256, attn_smem>>>(q, k, v, (__half*)att16);

        // Wo (splitk=3, reduce fused into add+LN)
        launch_gemm(att16, wo, bo + i * EDIM, NULL, part, ROWSM, EDIM, EDIM, 3, 0);
        add_ln_splitk_kernel<<<ROWSM, 256>>>(t, part, bo + i * EDIM,
                                             ln1_g + i * EDIM, ln1_b + i * EDIM,
                                             o1, (__half*)o116, MN_E);

        // FF1 (splitk=3 + relu reduce -> fp16 only)
        launch_gemm(o116, w1, b1 + i * FFDIM, NULL, part, ROWSM, FFDIM, EDIM, 3, 1);
        {
            int MN_F = ROWSM * FFDIM;
            splitk_reduce_kernel<<<(MN_F + 255) / 256, 256>>>(part, b1 + i * FFDIM,
                                                              NULL, (__half*)f116,
                                                              MN_F, FFDIM, 3, 1);
        }

        // FF2 (splitk=3, reduce fused into add+LN)
        launch_gemm(f116, w2, b2 + i * EDIM, NULL, part, ROWSM, EDIM, FFDIM, 3, 0);
        add_ln_splitk_kernel<<<ROWSM, 256>>>(o1, part, b2 + i * EDIM,
                                             ln2_g + i * EDIM, ln2_b + i * EDIM,
                                             t, (__half*)t16, MN_E);
    }

    head_kernel<<<BB, 256>>>(t, head_w, head_b, out);
}